// round 16
// baseline (speedup 1.0000x reference)
#include <cuda_runtime.h>
#include <cuda_fp16.h>
#include <cstdint>
#include <math.h>

#define B_   2
#define S_   2048
#define D_   4096
#define HQ_  32
#define HKV_ 8
#define HD_  128

// ---------------- scratch (static device globals; no allocations) ----------
__device__ __half g_xh[(size_t)B_ * S_ * D_];                  // x fp16
#define NQKV (HQ_ * HD_ + 2 * HKV_ * HD_)   // 6144
__device__ __half g_wqkvh[(size_t)NQKV * D_];                  // stacked qkv weights
__device__ __half g_woh[(size_t)D_ * HQ_ * HD_];
// rope'd Q, K, transposed V (all fp16)
__device__ __half g_qh[(size_t)B_ * HQ_ * S_ * HD_];   // [B,HQ,S,HD]
__device__ __half g_kh[(size_t)B_ * HKV_ * S_ * HD_];  // [B,HKV,S,HD]
__device__ __half g_vth[(size_t)B_ * HKV_ * HD_ * S_]; // [B,HKV,HD,S]
// attention output (fp16, [B,S,HQ,HD])
__device__ __half g_ah[(size_t)B_ * S_ * HQ_ * HD_];

// ---------------- PTX helpers (family-portable only) -----------------------
__device__ __forceinline__ uint32_t smem_u32(const void* p) {
    uint32_t a;
    asm("{ .reg .u64 t; cvta.to.shared.u64 t, %1; cvt.u32.u64 %0, t; }" : "=r"(a) : "l"(p));
    return a;
}
__device__ __forceinline__ void cp16(uint32_t s, const void* g) {
    asm volatile("cp.async.cg.shared.global [%0], [%1], 16;" :: "r"(s), "l"(g));
}
__device__ __forceinline__ void cp_commit() {
    asm volatile("cp.async.commit_group;" ::: "memory");
}
__device__ __forceinline__ void ldm_x4(uint32_t a, uint32_t& r0, uint32_t& r1,
                                       uint32_t& r2, uint32_t& r3) {
    asm volatile("ldmatrix.sync.aligned.m8n8.x4.shared.b16 {%0,%1,%2,%3}, [%4];"
                 : "=r"(r0), "=r"(r1), "=r"(r2), "=r"(r3) : "r"(a));
}
__device__ __forceinline__ void mma_f16(float& d0, float& d1, float& d2, float& d3,
                                        uint32_t a0, uint32_t a1, uint32_t a2, uint32_t a3,
                                        uint32_t b0, uint32_t b1) {
    asm volatile("mma.sync.aligned.m16n8k16.row.col.f32.f16.f16.f32 "
                 "{%0,%1,%2,%3}, {%4,%5,%6,%7}, {%8,%9}, {%0,%1,%2,%3};"
                 : "+f"(d0), "+f"(d1), "+f"(d2), "+f"(d3)
                 : "r"(a0), "r"(a1), "r"(a2), "r"(a3), "r"(b0), "r"(b1));
}
__device__ __forceinline__ uint32_t packh(float lo, float hi) {
    __half2 t = __floats2half2_rn(lo, hi);
    return *(uint32_t*)&t;
}

// ---------------------------------------------------------------------------
// merged fp32 -> fp16 convert: one launch for x, wq, wk, wv, wo.
// ---------------------------------------------------------------------------
#define N4X 4194304L
#define N4Q 4194304L
#define N4K 1048576L
#define N4O 4194304L
#define CONV_BLOCKS ((N4X + N4Q + 2 * N4K + N4O) / 512)   // 28672

__global__ void conv_all(const float* __restrict__ x,  const float* __restrict__ wq,
                         const float* __restrict__ wk, const float* __restrict__ wv,
                         const float* __restrict__ wo,
                         __half* __restrict__ xh, __half* __restrict__ wqkvh,
                         __half* __restrict__ woh)
{
    long base = (long)blockIdx.x * 512;
    const float* src;
    __half* dst;
    long off;
    if (base < N4X) {
        src = x; dst = xh; off = base;
    } else if (base < N4X + N4Q) {
        src = wq; dst = wqkvh; off = base - N4X;
    } else if (base < N4X + N4Q + N4K) {
        src = wk; dst = wqkvh + (size_t)HQ_ * HD_ * D_; off = base - (N4X + N4Q);
    } else if (base < N4X + N4Q + 2 * N4K) {
        src = wv; dst = wqkvh + (size_t)(HQ_ + HKV_) * HD_ * D_;
        off = base - (N4X + N4Q + N4K);
    } else {
        src = wo; dst = woh; off = base - (N4X + N4Q + 2 * N4K);
    }
    long i0 = off + threadIdx.x;
    long i1 = i0 + 256;
    float4 v0 = ((const float4*)src)[i0];
    float4 v1 = ((const float4*)src)[i1];
    __half2* p0 = (__half2*)(dst + 4 * i0);
    __half2* p1 = (__half2*)(dst + 4 * i1);
    p0[0] = __floats2half2_rn(v0.x, v0.y);
    p0[1] = __floats2half2_rn(v0.z, v0.w);
    p1[0] = __floats2half2_rn(v1.x, v1.y);
    p1[1] = __floats2half2_rn(v1.z, v1.w);
}

// ---------------------------------------------------------------------------
// fp16 GEMM (NT): CTA 128x128, 8 warps (2x4), warp tile 64x32, K-chunk 64.
// 1 CTA/SM, 255-reg budget, register-level fragment double buffering
// (LDSM for kk+1 issued before MMAs of kk), 5-stage cp.async pipeline.
// ---------------------------------------------------------------------------
#define KCH    64
#define RSTR   72                   // halves per smem row (64 data + 8 pad)
#define TILE_B (128 * RSTR * 2)     // 18432 B
#define STG_B  (2 * TILE_B)         // 36864 B
#define NSTG   5
#define GSMEM  (NSTG * STG_B)       // 184320 B
#define VTP    136                  // padded m-stride for V transpose tile

__global__ __launch_bounds__(256, 1) void gemm_fp16(
    const __half* __restrict__ Ah, const __half* __restrict__ Bh,
    float* __restrict__ Cf,
    __half* __restrict__ Qh, __half* __restrict__ Kh, __half* __restrict__ Vh,
    int M, int N, int K, int mode,
    const float* __restrict__ fc, const float* __restrict__ fs)
{
    extern __shared__ char smem[];
    const uint32_t sb = smem_u32(smem);
    const int tid = threadIdx.x;
    const int lane = tid & 31;
    const int wid = tid >> 5;
    const int wm = wid >> 2;
    const int wn = wid & 3;
    const int bm = blockIdx.y * 128;
    const int bn = blockIdx.x * 128;

    float acc[4][4][4];
#pragma unroll
    for (int i = 0; i < 4; i++)
#pragma unroll
        for (int j = 0; j < 4; j++)
#pragma unroll
            for (int c = 0; c < 4; c++) acc[i][j][c] = 0.f;

    const int iters = K / KCH;
    const int row0 = tid >> 3;
    const int col0 = tid & 7;

    // per-warp fragment base offsets (byte offsets within a stage's A/B tile)
    const uint32_t a_row_off = (wm * 64 + (lane & 15)) * (RSTR * 2);
    const uint32_t b_row_off = (wn * 32 + (lane & 15)) * (RSTR * 2);
    const uint32_t khalf = (lane >> 4) * 16;    // 8 halves = 16 bytes

#define PREFETCH(it_) do {                                                    \
    if ((it_) < iters) {                                                      \
        const uint32_t sob_ = sb + ((it_) % NSTG) * STG_B;                    \
        const int k0_ = (it_) * KCH;                                          \
        _Pragma("unroll")                                                     \
        for (int j_ = 0; j_ < 4; j_++) {                                      \
            int row_ = row0 + j_ * 32;                                        \
            uint32_t so_ = sob_ + row_ * (RSTR * 2) + col0 * 16;              \
            size_t ga_ = (size_t)(bm + row_) * K + k0_ + col0 * 8;            \
            size_t gb_ = (size_t)(bn + row_) * K + k0_ + col0 * 8;            \
            cp16(so_ + 0 * TILE_B, Ah + ga_);                                 \
            cp16(so_ + 1 * TILE_B, Bh + gb_);                                 \
        }                                                                     \
    }                                                                         \
    cp_commit();                                                              \
} while (0)

// load fragments for k-block kk_ of current stage into buffer fb_
#define LOADFRAG(fb_, kk_) do {                                               \
    const uint32_t kb_ = (kk_) * 32 + khalf;                                  \
    uint32_t r0_, r1_, r2_, r3_;                                              \
    ldm_x4(b_h + b_row_off + kb_, r0_, r1_, r2_, r3_);                        \
    bfr[fb_][0][0] = r0_; bfr[fb_][0][1] = r2_;                               \
    bfr[fb_][1][0] = r1_; bfr[fb_][1][1] = r3_;                               \
    ldm_x4(b_h + b_row_off + 16 * (RSTR * 2) + kb_, r0_, r1_, r2_, r3_);      \
    bfr[fb_][2][0] = r0_; bfr[fb_][2][1] = r2_;                               \
    bfr[fb_][3][0] = r1_; bfr[fb_][3][1] = r3_;                               \
    _Pragma("unroll")                                                         \
    for (int mf_ = 0; mf_ < 4; mf_++)                                         \
        ldm_x4(a_h + a_row_off + mf_ * 16 * (RSTR * 2) + kb_,                 \
               afr[fb_][mf_][0], afr[fb_][mf_][1],                            \
               afr[fb_][mf_][2], afr[fb_][mf_][3]);                           \
} while (0)

    PREFETCH(0);
    PREFETCH(1);
    PREFETCH(2);
    PREFETCH(3);

    uint32_t afr[2][4][4], bfr[2][4][2];

    for (int it = 0; it < iters; it++) {
        asm volatile("cp.async.wait_group 3;" ::: "memory");
        __syncthreads();
        PREFETCH(it + 4);   // writes stage (it-1)%5 — consumed last iter

        const uint32_t base = sb + (it % NSTG) * STG_B;
        const uint32_t a_h = base;
        const uint32_t b_h = base + TILE_B;

        LOADFRAG(0, 0);
#pragma unroll
        for (int kk = 0; kk < 4; kk++) {
            const int cur = kk & 1;
            if (kk < 3) LOADFRAG(!cur, kk + 1);
#pragma unroll
            for (int mf = 0; mf < 4; mf++)
#pragma unroll
                for (int nf = 0; nf < 4; nf++)
                    mma_f16(acc[mf][nf][0], acc[mf][nf][1], acc[mf][nf][2], acc[mf][nf][3],
                            afr[cur][mf][0], afr[cur][mf][1],
                            afr[cur][mf][2], afr[cur][mf][3],
                            bfr[cur][nf][0], bfr[cur][nf][1]);
        }
    }
#undef PREFETCH
#undef LOADFRAG

    const int qr = lane >> 2;
    const int qc = lane & 3;

    // ---- V tile: smem transpose then coalesced stores along S ----
    if (mode == 3 && bn >= HQ_ * HD_ + HKV_ * HD_) {
        __syncthreads();
        __half* T = (__half*)smem;
#pragma unroll
        for (int mf = 0; mf < 4; mf++)
#pragma unroll
            for (int half_ = 0; half_ < 2; half_++) {
                int ml = wm * 64 + mf * 16 + qr + half_ * 8;
#pragma unroll
                for (int nf = 0; nf < 4; nf++) {
                    int nl = wn * 32 + nf * 8 + 2 * qc;
                    float2 w = half_ ? make_float2(acc[mf][nf][2], acc[mf][nf][3])
                                     : make_float2(acc[mf][nf][0], acc[mf][nf][1]);
                    T[nl * VTP + ml] = __float2half_rn(w.x);
                    T[(nl + 1) * VTP + ml] = __float2half_rn(w.y);
                }
            }
        __syncthreads();
        int nv0 = bn - (HQ_ * HD_ + HKV_ * HD_);
        int h = nv0 >> 7;
        int b = bm >> 11;
        int s0 = bm & (S_ - 1);
        int r = tid >> 1;
        int cpart = (tid & 1) * 64;
        __half* dst = Vh + (((size_t)b * HKV_ + h) * HD_ + r) * S_ + s0 + cpart;
        const uint4* srcp = (const uint4*)(T + r * VTP + cpart);
#pragma unroll
        for (int u = 0; u < 8; u++)
            ((uint4*)dst)[u] = srcp[u];
        return;
    }

#pragma unroll
    for (int mf = 0; mf < 4; mf++) {
#pragma unroll
        for (int half_ = 0; half_ < 2; half_++) {
            int m = bm + wm * 64 + mf * 16 + qr + half_ * 8;
            if (mode == 0) {
                float* dst = Cf + (size_t)m * N + bn;
#pragma unroll
                for (int nf = 0; nf < 4; nf++) {
                    int n = wn * 32 + nf * 8 + 2 * qc;
                    float2 w = half_ ? make_float2(acc[mf][nf][2], acc[mf][nf][3])
                                     : make_float2(acc[mf][nf][0], acc[mf][nf][1]);
                    *(float2*)(dst + n) = w;
                }
            } else {
                int b = m >> 11;
                int s = m & (S_ - 1);
#pragma unroll
                for (int nf = 0; nf < 4; nf++) {
                    int n = bn + wn * 32 + nf * 8 + 2 * qc;
                    float2 w = half_ ? make_float2(acc[mf][nf][2], acc[mf][nf][3])
                                     : make_float2(acc[mf][nf][0], acc[mf][nf][1]);
                    if (n < HQ_ * HD_) {                    // Q: rope
                        int h = n >> 7;
                        int d = n & (HD_ - 1);
                        int i = d >> 1;
                        float c = fc[s * (HD_ / 2) + i];
                        float sn = fs[s * (HD_ / 2) + i];
                        float x0 = w.x * c - w.y * sn;
                        float x1 = w.x * sn + w.y * c;
                        size_t off = (((size_t)b * HQ_ + h) * S_ + s) * HD_ + d;
                        *(__half2*)(Qh + off) = __floats2half2_rn(x0, x1);
                    } else {                                 // K: rope
                        int nk = n - HQ_ * HD_;
                        int h = nk >> 7;
                        int d = nk & (HD_ - 1);
                        int i = d >> 1;
                        float c = fc[s * (HD_ / 2) + i];
                        float sn = fs[s * (HD_ / 2) + i];
                        float x0 = w.x * c - w.y * sn;
                        float x1 = w.x * sn + w.y * c;
                        size_t off = (((size_t)b * HKV_ + h) * S_ + s) * HD_ + d;
                        *(__half2*)(Kh + off) = __floats2half2_rn(x0, x1);
                    }
                }
            }
        }
    }
}

// ---------------------------------------------------------------------------
// Tensor-core flash attention (fp16 operands, fp32 accum) — round-15 config.
// Grid (S/128, B*HQ), block 256 (8 warps), 2 CTAs/SM, KT=64, 2-stage pipeline.
// ---------------------------------------------------------------------------
#define QT 128
#define KT 64
#define QROW_B 272
#define VROW_B 144
#define QTILE_B (QT * QROW_B)      // 34816
#define KTILE_B (KT * QROW_B)      // 17408
#define VTILE_B (128 * VROW_B)     // 18432
#define KVSTG_B (KTILE_B + VTILE_B)           // 35840
#define OFF_KV  QTILE_B                       // 34816
#define ATT_SMEM (OFF_KV + 2 * KVSTG_B)       // 106496

__global__ __launch_bounds__(256, 2) void attn_mma5(
    const __half* __restrict__ Qh_g,
    const __half* __restrict__ Kh_g,
    const __half* __restrict__ Vh_g,
    __half* __restrict__ Oh)
{
    extern __shared__ char smem[];
    const uint32_t sb = smem_u32(smem);
    const int bh = blockIdx.y;
    const int b = bh >> 5;
    const int h = bh & (HQ_ - 1);
    const int kvh = h >> 2;
    const int q0 = blockIdx.x * QT;
    const int tid = threadIdx.x;
    const int lane = tid & 31;
    const int warp = tid >> 5;

    const __half* qh = Qh_g + (((size_t)b * HQ_ + h) * S_ + q0) * HD_;
    const __half* kh = Kh_g + ((size_t)b * HKV_ + kvh) * S_ * HD_;
    const __half* vh = Vh_g + ((size_t)b * HKV_ + kvh) * HD_ * S_;

    const int T = S_ / KT;   // 32

#pragma unroll
    for (int i = 0; i < 8; i++) {
        int lin = tid + i * 256;
        int r = lin >> 4, c = lin & 15;
        cp16(sb + r * QROW_B + c * 16, qh + (size_t)r * HD_ + c * 8);
    }
    cp_commit();

#define STAGE_KV(t_) do {                                                     \
    if ((t_) < T) {                                                           \
        int t0_ = (t_) * KT;                                                  \
        uint32_t kb_ = sb + OFF_KV + ((t_) & 1) * KVSTG_B;                    \
        uint32_t vb_ = kb_ + KTILE_B;                                         \
        _Pragma("unroll")                                                     \
        for (int i_ = 0; i_ < 4; i_++) {                                      \
            int lin_ = tid + i_ * 256;                                        \
            int r_ = lin_ >> 4, c_ = lin_ & 15;                               \
            cp16(kb_ + r_ * QROW_B + c_ * 16, kh + (size_t)(t0_ + r_) * HD_ + c_ * 8); \
            int d_ = lin_ >> 3, c2_ = lin_ & 7;                               \
            cp16(vb_ + d_ * VROW_B + c2_ * 16, vh + (size_t)d_ * S_ + t0_ + c2_ * 8); \
        }                                                                     \
    }                                                                         \
    cp_commit();                                                              \
} while (0)

    STAGE_KV(0);
    STAGE_KV(1);

    float o[16][4];
#pragma unroll
    for (int t = 0; t < 16; t++)
#pragma unroll
        for (int c = 0; c < 4; c++) o[t][c] = 0.f;
    float m0 = -1e30f, m1 = -1e30f, l0v = 0.f, l1v = 0.f;

    const float scale = 0.08838834764831845f;
    const uint32_t qrow_off = (warp * 16 + (lane & 15)) * QROW_B;
    const uint32_t kcol_off = (lane >> 4) * 16;

    for (int t = 0; t < T; t++) {
        asm volatile("cp.async.wait_group 1;" ::: "memory");
        __syncthreads();

        const uint32_t ukh = sb + OFF_KV + (t & 1) * KVSTG_B;
        const uint32_t uvh = ukh + KTILE_B;

        float sc[8][4];
#pragma unroll
        for (int j = 0; j < 8; j++)
#pragma unroll
            for (int c = 0; c < 4; c++) sc[j][c] = 0.f;

#pragma unroll
        for (int ks = 0; ks < 8; ks++) {
            const uint32_t kb_off = ks * 32 + kcol_off;
            uint32_t qa[4];
            ldm_x4(sb + qrow_off + kb_off, qa[0], qa[1], qa[2], qa[3]);
#pragma unroll
            for (int np = 0; np < 4; np++) {
                uint32_t roff = (np * 16 + (lane & 15)) * QROW_B + kb_off;
                uint32_t r0, r1, r2, r3;
                ldm_x4(ukh + roff, r0, r1, r2, r3);
                mma_f16(sc[2*np][0], sc[2*np][1], sc[2*np][2], sc[2*np][3],
                        qa[0], qa[1], qa[2], qa[3], r0, r2);
                mma_f16(sc[2*np+1][0], sc[2*np+1][1], sc[2*np+1][2], sc[2*np+1][3],
                        qa[0], qa[1], qa[2], qa[3], r1, r3);
            }
        }

        float mx0 = -1e30f, mx1 = -1e30f;
#pragma unroll
        for (int j = 0; j < 8; j++) {
#pragma unroll
            for (int c = 0; c < 4; c++) sc[j][c] *= scale;
            mx0 = fmaxf(mx0, fmaxf(sc[j][0], sc[j][1]));
            mx1 = fmaxf(mx1, fmaxf(sc[j][2], sc[j][3]));
        }
        mx0 = fmaxf(mx0, __shfl_xor_sync(0xffffffffu, mx0, 1));
        mx0 = fmaxf(mx0, __shfl_xor_sync(0xffffffffu, mx0, 2));
        mx1 = fmaxf(mx1, __shfl_xor_sync(0xffffffffu, mx1, 1));
        mx1 = fmaxf(mx1, __shfl_xor_sync(0xffffffffu, mx1, 2));
        float mn0 = fmaxf(m0, mx0), mn1 = fmaxf(m1, mx1);
        float al0 = __expf(m0 - mn0), al1 = __expf(m1 - mn1);
        m0 = mn0; m1 = mn1;
        float rs0 = 0.f, rs1 = 0.f;
#pragma unroll
        for (int j = 0; j < 8; j++) {
            sc[j][0] = __expf(sc[j][0] - m0);
            sc[j][1] = __expf(sc[j][1] - m0);
            sc[j][2] = __expf(sc[j][2] - m1);
            sc[j][3] = __expf(sc[j][3] - m1);
            rs0 += sc[j][0] + sc[j][1];
            rs1 += sc[j][2] + sc[j][3];
        }
        rs0 += __shfl_xor_sync(0xffffffffu, rs0, 1);
        rs0 += __shfl_xor_sync(0xffffffffu, rs0, 2);
        rs1 += __shfl_xor_sync(0xffffffffu, rs1, 1);
        rs1 += __shfl_xor_sync(0xffffffffu, rs1, 2);
        l0v = l0v * al0 + rs0;
        l1v = l1v * al1 + rs1;
#pragma unroll
        for (int tt = 0; tt < 16; tt++) {
            o[tt][0] *= al0; o[tt][1] *= al0;
            o[tt][2] *= al1; o[tt][3] *= al1;
        }

#pragma unroll
        for (int kb = 0; kb < 4; kb++) {
            uint32_t ph0 = packh(sc[2*kb][0],   sc[2*kb][1]);
            uint32_t ph1 = packh(sc[2*kb][2],   sc[2*kb][3]);
            uint32_t ph2 = packh(sc[2*kb+1][0], sc[2*kb+1][1]);
            uint32_t ph3 = packh(sc[2*kb+1][2], sc[2*kb+1][3]);
            const uint32_t kb_off = kb * 32 + kcol_off;
#pragma unroll
            for (int np = 0; np < 8; np++) {
                uint32_t roff = (np * 16 + (lane & 15)) * VROW_B + kb_off;
                uint32_t r0, r1, r2, r3;
                ldm_x4(uvh + roff, r0, r1, r2, r3);
                mma_f16(o[2*np][0], o[2*np][1], o[2*np][2], o[2*np][3],
                        ph0, ph1, ph2, ph3, r0, r2);
                mma_f16(o[2*np+1][0], o[2*np+1][1], o[2*np+1][2], o[2*np+1][3],
                        ph0, ph1, ph2, ph3, r1, r3);
            }
        }

        __syncthreads();
        STAGE_KV(t + 2);
    }
#undef STAGE_KV

    float inv0 = 1.0f / l0v, inv1 = 1.0f / l1v;
    int s0 = q0 + warp * 16 + (lane >> 2);
    int s1 = s0 + 8;
    size_t base0 = (((size_t)b * S_ + s0) * HQ_ + h) * HD_ + 2 * (lane & 3);
    size_t base1 = (((size_t)b * S_ + s1) * HQ_ + h) * HD_ + 2 * (lane & 3);
#pragma unroll
    for (int t = 0; t < 16; t++) {
        *(__half2*)(Oh + base0 + 8 * t) =
            __floats2half2_rn(o[t][0] * inv0, o[t][1] * inv0);
        *(__half2*)(Oh + base1 + 8 * t) =
            __floats2half2_rn(o[t][2] * inv1, o[t][3] * inv1);
    }
}

// ---------------------------------------------------------------------------
extern "C" void kernel_launch(void* const* d_in, const int* in_sizes, int n_in,
                              void* d_out, int out_size)
{
    const float* x  = (const float*)d_in[0];
    const float* wq = (const float*)d_in[1];
    const float* wk = (const float*)d_in[2];
    const float* wv = (const float*)d_in[3];
    const float* wo = (const float*)d_in[4];
    const float* fc = (const float*)d_in[5];
    const float* fs = (const float*)d_in[6];
    float* out = (float*)d_out;

    __half *xh, *wqkvh, *woh, *qh, *kh, *vth, *ah;
    cudaGetSymbolAddress((void**)&xh, g_xh);
    cudaGetSymbolAddress((void**)&wqkvh, g_wqkvh);
    cudaGetSymbolAddress((void**)&woh, g_woh);
    cudaGetSymbolAddress((void**)&qh, g_qh);
    cudaGetSymbolAddress((void**)&kh, g_kh);
    cudaGetSymbolAddress((void**)&vth, g_vth);
    cudaGetSymbolAddress((void**)&ah, g_ah);

    const int M = B_ * S_;  // 4096

    // merged converts (one launch)
    conv_all<<<(unsigned)CONV_BLOCKS, 256>>>(x, wq, wk, wv, wo, xh, wqkvh, woh);

    cudaFuncSetAttribute(gemm_fp16, cudaFuncAttributeMaxDynamicSharedMemorySize, GSMEM);

    // fused QKV projection (rope + layout in epilogue; V via smem transpose)
    gemm_fp16<<<dim3(NQKV / 128, M / 128), 256, GSMEM>>>(
        xh, wqkvh, nullptr, qh, kh, vth, M, NQKV, D_, 3, fc, fs);

    // tensor-core attention (KT=64)
    cudaFuncSetAttribute(attn_mma5, cudaFuncAttributeMaxDynamicSharedMemorySize, ATT_SMEM);
    attn_mma5<<<dim3(S_ / QT, B_ * HQ_), 256, ATT_SMEM>>>(qh, kh, vth, ah);

    // output projection -> d_out (fp32)
    gemm_fp16<<<dim3(D_ / 128, M / 128), 256, GSMEM>>>(
        ah, woh, out, nullptr, nullptr, nullptr, M, D_, D_, 0, fc, fs);
}

// round 17
// speedup vs baseline: 1.1551x; 1.1551x over previous
#include <cuda_runtime.h>
#include <cuda_fp16.h>
#include <cstdint>
#include <math.h>

#define B_   2
#define S_   2048
#define D_   4096
#define HQ_  32
#define HKV_ 8
#define HD_  128

// ---------------- scratch (static device globals; no allocations) ----------
__device__ __half g_xh[(size_t)B_ * S_ * D_];                  // x fp16
#define NQKV (HQ_ * HD_ + 2 * HKV_ * HD_)   // 6144
__device__ __half g_wqkvh[(size_t)NQKV * D_];                  // stacked qkv weights
__device__ __half g_woh[(size_t)D_ * HQ_ * HD_];
// rope'd Q, K, transposed V (all fp16)
__device__ __half g_qh[(size_t)B_ * HQ_ * S_ * HD_];   // [B,HQ,S,HD]
__device__ __half g_kh[(size_t)B_ * HKV_ * S_ * HD_];  // [B,HKV,S,HD]
__device__ __half g_vth[(size_t)B_ * HKV_ * HD_ * S_]; // [B,HKV,HD,S]
// attention output (fp16, [B,S,HQ,HD])
__device__ __half g_ah[(size_t)B_ * S_ * HQ_ * HD_];

// ---------------- PTX helpers (family-portable only) -----------------------
__device__ __forceinline__ uint32_t smem_u32(const void* p) {
    uint32_t a;
    asm("{ .reg .u64 t; cvta.to.shared.u64 t, %1; cvt.u32.u64 %0, t; }" : "=r"(a) : "l"(p));
    return a;
}
__device__ __forceinline__ void cp16(uint32_t s, const void* g) {
    asm volatile("cp.async.cg.shared.global [%0], [%1], 16;" :: "r"(s), "l"(g));
}
__device__ __forceinline__ void cp_commit() {
    asm volatile("cp.async.commit_group;" ::: "memory");
}
__device__ __forceinline__ void ldm_x4(uint32_t a, uint32_t& r0, uint32_t& r1,
                                       uint32_t& r2, uint32_t& r3) {
    asm volatile("ldmatrix.sync.aligned.m8n8.x4.shared.b16 {%0,%1,%2,%3}, [%4];"
                 : "=r"(r0), "=r"(r1), "=r"(r2), "=r"(r3) : "r"(a));
}
__device__ __forceinline__ void mma_f16(float& d0, float& d1, float& d2, float& d3,
                                        uint32_t a0, uint32_t a1, uint32_t a2, uint32_t a3,
                                        uint32_t b0, uint32_t b1) {
    asm volatile("mma.sync.aligned.m16n8k16.row.col.f32.f16.f16.f32 "
                 "{%0,%1,%2,%3}, {%4,%5,%6,%7}, {%8,%9}, {%0,%1,%2,%3};"
                 : "+f"(d0), "+f"(d1), "+f"(d2), "+f"(d3)
                 : "r"(a0), "r"(a1), "r"(a2), "r"(a3), "r"(b0), "r"(b1));
}
__device__ __forceinline__ uint32_t packh(float lo, float hi) {
    __half2 t = __floats2half2_rn(lo, hi);
    return *(uint32_t*)&t;
}

// ---------------------------------------------------------------------------
// merged fp32 -> fp16 convert: one launch for x, wq, wk, wv, wo.
// ---------------------------------------------------------------------------
#define N4X 4194304L
#define N4Q 4194304L
#define N4K 1048576L
#define N4O 4194304L
#define CONV_BLOCKS ((N4X + N4Q + 2 * N4K + N4O) / 512)   // 28672

__global__ void conv_all(const float* __restrict__ x,  const float* __restrict__ wq,
                         const float* __restrict__ wk, const float* __restrict__ wv,
                         const float* __restrict__ wo,
                         __half* __restrict__ xh, __half* __restrict__ wqkvh,
                         __half* __restrict__ woh)
{
    long base = (long)blockIdx.x * 512;
    const float* src;
    __half* dst;
    long off;
    if (base < N4X) {
        src = x; dst = xh; off = base;
    } else if (base < N4X + N4Q) {
        src = wq; dst = wqkvh; off = base - N4X;
    } else if (base < N4X + N4Q + N4K) {
        src = wk; dst = wqkvh + (size_t)HQ_ * HD_ * D_; off = base - (N4X + N4Q);
    } else if (base < N4X + N4Q + 2 * N4K) {
        src = wv; dst = wqkvh + (size_t)(HQ_ + HKV_) * HD_ * D_;
        off = base - (N4X + N4Q + N4K);
    } else {
        src = wo; dst = woh; off = base - (N4X + N4Q + 2 * N4K);
    }
    long i0 = off + threadIdx.x;
    long i1 = i0 + 256;
    float4 v0 = ((const float4*)src)[i0];
    float4 v1 = ((const float4*)src)[i1];
    __half2* p0 = (__half2*)(dst + 4 * i0);
    __half2* p1 = (__half2*)(dst + 4 * i1);
    p0[0] = __floats2half2_rn(v0.x, v0.y);
    p0[1] = __floats2half2_rn(v0.z, v0.w);
    p1[0] = __floats2half2_rn(v1.x, v1.y);
    p1[1] = __floats2half2_rn(v1.z, v1.w);
}

// ---------------------------------------------------------------------------
// fp16 GEMM (NT) — round-15 config (best measured): CTA 128x128, 8 warps
// (2x4), warp tile 64x32, K-chunk 64, 2 CTAs/SM, 3-stage pipeline.
// PREFETCH moved inside the kk loop (kk==1) so post-barrier LDSM starts
// immediately and cp.async issue overlaps kk=0 MMAs.
// ---------------------------------------------------------------------------
#define KCH    64
#define RSTR   72                   // halves per smem row (64 data + 8 pad)
#define TILE_B (128 * RSTR * 2)     // 18432 B
#define STG_B  (2 * TILE_B)         // 36864 B
#define NSTG   3
#define GSMEM  (NSTG * STG_B)       // 110592 B
#define VTP    136                  // padded m-stride for V transpose tile

__global__ __launch_bounds__(256, 2) void gemm_fp16(
    const __half* __restrict__ Ah, const __half* __restrict__ Bh,
    float* __restrict__ Cf,
    __half* __restrict__ Qh, __half* __restrict__ Kh, __half* __restrict__ Vh,
    int M, int N, int K, int mode,
    const float* __restrict__ fc, const float* __restrict__ fs)
{
    extern __shared__ char smem[];
    const uint32_t sb = smem_u32(smem);
    const int tid = threadIdx.x;
    const int lane = tid & 31;
    const int wid = tid >> 5;
    const int wm = wid >> 2;
    const int wn = wid & 3;
    const int bm = blockIdx.y * 128;
    const int bn = blockIdx.x * 128;

    float acc[4][4][4];
#pragma unroll
    for (int i = 0; i < 4; i++)
#pragma unroll
        for (int j = 0; j < 4; j++)
#pragma unroll
            for (int c = 0; c < 4; c++) acc[i][j][c] = 0.f;

    const int iters = K / KCH;
    const int row0 = tid >> 3;
    const int col0 = tid & 7;

#define PREFETCH(it_) do {                                                    \
    if ((it_) < iters) {                                                      \
        const uint32_t sob_ = sb + ((it_) % NSTG) * STG_B;                    \
        const int k0_ = (it_) * KCH;                                          \
        _Pragma("unroll")                                                     \
        for (int j_ = 0; j_ < 4; j_++) {                                      \
            int row_ = row0 + j_ * 32;                                        \
            uint32_t so_ = sob_ + row_ * (RSTR * 2) + col0 * 16;              \
            size_t ga_ = (size_t)(bm + row_) * K + k0_ + col0 * 8;            \
            size_t gb_ = (size_t)(bn + row_) * K + k0_ + col0 * 8;            \
            cp16(so_ + 0 * TILE_B, Ah + ga_);                                 \
            cp16(so_ + 1 * TILE_B, Bh + gb_);                                 \
        }                                                                     \
    }                                                                         \
    cp_commit();                                                              \
} while (0)

    PREFETCH(0);
    PREFETCH(1);

    for (int it = 0; it < iters; it++) {
        asm volatile("cp.async.wait_group 1;" ::: "memory");
        __syncthreads();

        const uint32_t base = sb + (it % NSTG) * STG_B;
        const uint32_t a_h = base;
        const uint32_t b_h = base + TILE_B;

#pragma unroll
        for (int kk = 0; kk < 4; kk++) {
            if (kk == 1) PREFETCH(it + 2);   // overlap cp.async issue w/ kk0 MMAs
            const int kc = kk * 16 + (lane >> 4) * 8;
            uint32_t a[4][4], bhf[4][2];
#pragma unroll
            for (int nq = 0; nq < 2; nq++) {
                int row = wn * 32 + nq * 16 + (lane & 15);
                uint32_t off = row * (RSTR * 2) + kc * 2;
                uint32_t r0, r1, r2, r3;
                ldm_x4(b_h + off, r0, r1, r2, r3);
                bhf[nq * 2][0] = r0; bhf[nq * 2][1] = r2;
                bhf[nq * 2 + 1][0] = r1; bhf[nq * 2 + 1][1] = r3;
            }
#pragma unroll
            for (int mf = 0; mf < 4; mf++) {
                int row = wm * 64 + mf * 16 + (lane & 15);
                ldm_x4(a_h + row * (RSTR * 2) + kc * 2,
                       a[mf][0], a[mf][1], a[mf][2], a[mf][3]);
            }
#pragma unroll
            for (int mf = 0; mf < 4; mf++)
#pragma unroll
                for (int nf = 0; nf < 4; nf++)
                    mma_f16(acc[mf][nf][0], acc[mf][nf][1], acc[mf][nf][2], acc[mf][nf][3],
                            a[mf][0], a[mf][1], a[mf][2], a[mf][3],
                            bhf[nf][0], bhf[nf][1]);
        }
    }
#undef PREFETCH

    const int qr = lane >> 2;
    const int qc = lane & 3;

    // ---- V tile: smem transpose then coalesced stores along S ----
    if (mode == 3 && bn >= HQ_ * HD_ + HKV_ * HD_) {
        __syncthreads();
        __half* T = (__half*)smem;
#pragma unroll
        for (int mf = 0; mf < 4; mf++)
#pragma unroll
            for (int half_ = 0; half_ < 2; half_++) {
                int ml = wm * 64 + mf * 16 + qr + half_ * 8;
#pragma unroll
                for (int nf = 0; nf < 4; nf++) {
                    int nl = wn * 32 + nf * 8 + 2 * qc;
                    float2 w = half_ ? make_float2(acc[mf][nf][2], acc[mf][nf][3])
                                     : make_float2(acc[mf][nf][0], acc[mf][nf][1]);
                    T[nl * VTP + ml] = __float2half_rn(w.x);
                    T[(nl + 1) * VTP + ml] = __float2half_rn(w.y);
                }
            }
        __syncthreads();
        int nv0 = bn - (HQ_ * HD_ + HKV_ * HD_);
        int h = nv0 >> 7;
        int b = bm >> 11;
        int s0 = bm & (S_ - 1);
        int r = tid >> 1;
        int cpart = (tid & 1) * 64;
        __half* dst = Vh + (((size_t)b * HKV_ + h) * HD_ + r) * S_ + s0 + cpart;
        const uint4* srcp = (const uint4*)(T + r * VTP + cpart);
#pragma unroll
        for (int u = 0; u < 8; u++)
            ((uint4*)dst)[u] = srcp[u];
        return;
    }

#pragma unroll
    for (int mf = 0; mf < 4; mf++) {
#pragma unroll
        for (int half_ = 0; half_ < 2; half_++) {
            int m = bm + wm * 64 + mf * 16 + qr + half_ * 8;
            if (mode == 0) {
                float* dst = Cf + (size_t)m * N + bn;
#pragma unroll
                for (int nf = 0; nf < 4; nf++) {
                    int n = wn * 32 + nf * 8 + 2 * qc;
                    float2 w = half_ ? make_float2(acc[mf][nf][2], acc[mf][nf][3])
                                     : make_float2(acc[mf][nf][0], acc[mf][nf][1]);
                    *(float2*)(dst + n) = w;
                }
            } else {
                int b = m >> 11;
                int s = m & (S_ - 1);
#pragma unroll
                for (int nf = 0; nf < 4; nf++) {
                    int n = bn + wn * 32 + nf * 8 + 2 * qc;
                    float2 w = half_ ? make_float2(acc[mf][nf][2], acc[mf][nf][3])
                                     : make_float2(acc[mf][nf][0], acc[mf][nf][1]);
                    if (n < HQ_ * HD_) {                    // Q: rope
                        int h = n >> 7;
                        int d = n & (HD_ - 1);
                        int i = d >> 1;
                        float c = fc[s * (HD_ / 2) + i];
                        float sn = fs[s * (HD_ / 2) + i];
                        float x0 = w.x * c - w.y * sn;
                        float x1 = w.x * sn + w.y * c;
                        size_t off = (((size_t)b * HQ_ + h) * S_ + s) * HD_ + d;
                        *(__half2*)(Qh + off) = __floats2half2_rn(x0, x1);
                    } else {                                 // K: rope
                        int nk = n - HQ_ * HD_;
                        int h = nk >> 7;
                        int d = nk & (HD_ - 1);
                        int i = d >> 1;
                        float c = fc[s * (HD_ / 2) + i];
                        float sn = fs[s * (HD_ / 2) + i];
                        float x0 = w.x * c - w.y * sn;
                        float x1 = w.x * sn + w.y * c;
                        size_t off = (((size_t)b * HKV_ + h) * S_ + s) * HD_ + d;
                        *(__half2*)(Kh + off) = __floats2half2_rn(x0, x1);
                    }
                }
            }
        }
    }
}

// ---------------------------------------------------------------------------
// Tensor-core flash attention (fp16 operands, fp32 accum) — round-15 config.
// Grid (S/128, B*HQ), block 256 (8 warps), 2 CTAs/SM, KT=64, 2-stage pipeline.
// ---------------------------------------------------------------------------
#define QT 128
#define KT 64
#define QROW_B 272
#define VROW_B 144
#define QTILE_B (QT * QROW_B)      // 34816
#define KTILE_B (KT * QROW_B)      // 17408
#define VTILE_B (128 * VROW_B)     // 18432
#define KVSTG_B (KTILE_B + VTILE_B)           // 35840
#define OFF_KV  QTILE_B                       // 34816
#define ATT_SMEM (OFF_KV + 2 * KVSTG_B)       // 106496

__global__ __launch_bounds__(256, 2) void attn_mma5(
    const __half* __restrict__ Qh_g,
    const __half* __restrict__ Kh_g,
    const __half* __restrict__ Vh_g,
    __half* __restrict__ Oh)
{
    extern __shared__ char smem[];
    const uint32_t sb = smem_u32(smem);
    const int bh = blockIdx.y;
    const int b = bh >> 5;
    const int h = bh & (HQ_ - 1);
    const int kvh = h >> 2;
    const int q0 = blockIdx.x * QT;
    const int tid = threadIdx.x;
    const int lane = tid & 31;
    const int warp = tid >> 5;

    const __half* qh = Qh_g + (((size_t)b * HQ_ + h) * S_ + q0) * HD_;
    const __half* kh = Kh_g + ((size_t)b * HKV_ + kvh) * S_ * HD_;
    const __half* vh = Vh_g + ((size_t)b * HKV_ + kvh) * HD_ * S_;

    const int T = S_ / KT;   // 32

#pragma unroll
    for (int i = 0; i < 8; i++) {
        int lin = tid + i * 256;
        int r = lin >> 4, c = lin & 15;
        cp16(sb + r * QROW_B + c * 16, qh + (size_t)r * HD_ + c * 8);
    }
    cp_commit();

#define STAGE_KV(t_) do {                                                     \
    if ((t_) < T) {                                                           \
        int t0_ = (t_) * KT;                                                  \
        uint32_t kb_ = sb + OFF_KV + ((t_) & 1) * KVSTG_B;                    \
        uint32_t vb_ = kb_ + KTILE_B;                                         \
        _Pragma("unroll")                                                     \
        for (int i_ = 0; i_ < 4; i_++) {                                      \
            int lin_ = tid + i_ * 256;                                        \
            int r_ = lin_ >> 4, c_ = lin_ & 15;                               \
            cp16(kb_ + r_ * QROW_B + c_ * 16, kh + (size_t)(t0_ + r_) * HD_ + c_ * 8); \
            int d_ = lin_ >> 3, c2_ = lin_ & 7;                               \
            cp16(vb_ + d_ * VROW_B + c2_ * 16, vh + (size_t)d_ * S_ + t0_ + c2_ * 8); \
        }                                                                     \
    }                                                                         \
    cp_commit();                                                              \
} while (0)

    STAGE_KV(0);
    STAGE_KV(1);

    float o[16][4];
#pragma unroll
    for (int t = 0; t < 16; t++)
#pragma unroll
        for (int c = 0; c < 4; c++) o[t][c] = 0.f;
    float m0 = -1e30f, m1 = -1e30f, l0v = 0.f, l1v = 0.f;

    const float scale = 0.08838834764831845f;
    const uint32_t qrow_off = (warp * 16 + (lane & 15)) * QROW_B;
    const uint32_t kcol_off = (lane >> 4) * 16;

    for (int t = 0; t < T; t++) {
        asm volatile("cp.async.wait_group 1;" ::: "memory");
        __syncthreads();

        const uint32_t ukh = sb + OFF_KV + (t & 1) * KVSTG_B;
        const uint32_t uvh = ukh + KTILE_B;

        float sc[8][4];
#pragma unroll
        for (int j = 0; j < 8; j++)
#pragma unroll
            for (int c = 0; c < 4; c++) sc[j][c] = 0.f;

#pragma unroll
        for (int ks = 0; ks < 8; ks++) {
            const uint32_t kb_off = ks * 32 + kcol_off;
            uint32_t qa[4];
            ldm_x4(sb + qrow_off + kb_off, qa[0], qa[1], qa[2], qa[3]);
#pragma unroll
            for (int np = 0; np < 4; np++) {
                uint32_t roff = (np * 16 + (lane & 15)) * QROW_B + kb_off;
                uint32_t r0, r1, r2, r3;
                ldm_x4(ukh + roff, r0, r1, r2, r3);
                mma_f16(sc[2*np][0], sc[2*np][1], sc[2*np][2], sc[2*np][3],
                        qa[0], qa[1], qa[2], qa[3], r0, r2);
                mma_f16(sc[2*np+1][0], sc[2*np+1][1], sc[2*np+1][2], sc[2*np+1][3],
                        qa[0], qa[1], qa[2], qa[3], r1, r3);
            }
        }

        float mx0 = -1e30f, mx1 = -1e30f;
#pragma unroll
        for (int j = 0; j < 8; j++) {
#pragma unroll
            for (int c = 0; c < 4; c++) sc[j][c] *= scale;
            mx0 = fmaxf(mx0, fmaxf(sc[j][0], sc[j][1]));
            mx1 = fmaxf(mx1, fmaxf(sc[j][2], sc[j][3]));
        }
        mx0 = fmaxf(mx0, __shfl_xor_sync(0xffffffffu, mx0, 1));
        mx0 = fmaxf(mx0, __shfl_xor_sync(0xffffffffu, mx0, 2));
        mx1 = fmaxf(mx1, __shfl_xor_sync(0xffffffffu, mx1, 1));
        mx1 = fmaxf(mx1, __shfl_xor_sync(0xffffffffu, mx1, 2));
        float mn0 = fmaxf(m0, mx0), mn1 = fmaxf(m1, mx1);
        float al0 = __expf(m0 - mn0), al1 = __expf(m1 - mn1);
        m0 = mn0; m1 = mn1;
        float rs0 = 0.f, rs1 = 0.f;
#pragma unroll
        for (int j = 0; j < 8; j++) {
            sc[j][0] = __expf(sc[j][0] - m0);
            sc[j][1] = __expf(sc[j][1] - m0);
            sc[j][2] = __expf(sc[j][2] - m1);
            sc[j][3] = __expf(sc[j][3] - m1);
            rs0 += sc[j][0] + sc[j][1];
            rs1 += sc[j][2] + sc[j][3];
        }
        rs0 += __shfl_xor_sync(0xffffffffu, rs0, 1);
        rs0 += __shfl_xor_sync(0xffffffffu, rs0, 2);
        rs1 += __shfl_xor_sync(0xffffffffu, rs1, 1);
        rs1 += __shfl_xor_sync(0xffffffffu, rs1, 2);
        l0v = l0v * al0 + rs0;
        l1v = l1v * al1 + rs1;
#pragma unroll
        for (int tt = 0; tt < 16; tt++) {
            o[tt][0] *= al0; o[tt][1] *= al0;
            o[tt][2] *= al1; o[tt][3] *= al1;
        }

#pragma unroll
        for (int kb = 0; kb < 4; kb++) {
            uint32_t ph0 = packh(sc[2*kb][0],   sc[2*kb][1]);
            uint32_t ph1 = packh(sc[2*kb][2],   sc[2*kb][3]);
            uint32_t ph2 = packh(sc[2*kb+1][0], sc[2*kb+1][1]);
            uint32_t ph3 = packh(sc[2*kb+1][2], sc[2*kb+1][3]);
            const uint32_t kb_off = kb * 32 + kcol_off;
#pragma unroll
            for (int np = 0; np < 8; np++) {
                uint32_t roff = (np * 16 + (lane & 15)) * VROW_B + kb_off;
                uint32_t r0, r1, r2, r3;
                ldm_x4(uvh + roff, r0, r1, r2, r3);
                mma_f16(o[2*np][0], o[2*np][1], o[2*np][2], o[2*np][3],
                        ph0, ph1, ph2, ph3, r0, r2);
                mma_f16(o[2*np+1][0], o[2*np+1][1], o[2*np+1][2], o[2*np+1][3],
                        ph0, ph1, ph2, ph3, r1, r3);
            }
        }

        __syncthreads();
        STAGE_KV(t + 2);
    }
#undef STAGE_KV

    float inv0 = 1.0f / l0v, inv1 = 1.0f / l1v;
    int s0 = q0 + warp * 16 + (lane >> 2);
    int s1 = s0 + 8;
    size_t base0 = (((size_t)b * S_ + s0) * HQ_ + h) * HD_ + 2 * (lane & 3);
    size_t base1 = (((size_t)b * S_ + s1) * HQ_ + h) * HD_ + 2 * (lane & 3);
#pragma unroll
    for (int t = 0; t < 16; t++) {
        *(__half2*)(Oh + base0 + 8 * t) =
            __floats2half2_rn(o[t][0] * inv0, o[t][1] * inv0);
        *(__half2*)(Oh + base1 + 8 * t) =
            __floats2half2_rn(o[t][2] * inv1, o[t][3] * inv1);
    }
}

// ---------------------------------------------------------------------------
extern "C" void kernel_launch(void* const* d_in, const int* in_sizes, int n_in,
                              void* d_out, int out_size)
{
    const float* x  = (const float*)d_in[0];
    const float* wq = (const float*)d_in[1];
    const float* wk = (const float*)d_in[2];
    const float* wv = (const float*)d_in[3];
    const float* wo = (const float*)d_in[4];
    const float* fc = (const float*)d_in[5];
    const float* fs = (const float*)d_in[6];
    float* out = (float*)d_out;

    __half *xh, *wqkvh, *woh, *qh, *kh, *vth, *ah;
    cudaGetSymbolAddress((void**)&xh, g_xh);
    cudaGetSymbolAddress((void**)&wqkvh, g_wqkvh);
    cudaGetSymbolAddress((void**)&woh, g_woh);
    cudaGetSymbolAddress((void**)&qh, g_qh);
    cudaGetSymbolAddress((void**)&kh, g_kh);
    cudaGetSymbolAddress((void**)&vth, g_vth);
    cudaGetSymbolAddress((void**)&ah, g_ah);

    const int M = B_ * S_;  // 4096

    // merged converts (one launch)
    conv_all<<<(unsigned)CONV_BLOCKS, 256>>>(x, wq, wk, wv, wo, xh, wqkvh, woh);

    cudaFuncSetAttribute(gemm_fp16, cudaFuncAttributeMaxDynamicSharedMemorySize, GSMEM);

    // fused QKV projection (rope + layout in epilogue; V via smem transpose)
    gemm_fp16<<<dim3(NQKV / 128, M / 128), 256, GSMEM>>>(
        xh, wqkvh, nullptr, qh, kh, vth, M, NQKV, D_, 3, fc, fs);

    // tensor-core attention (KT=64)
    cudaFuncSetAttribute(attn_mma5, cudaFuncAttributeMaxDynamicSharedMemorySize, ATT_SMEM);
    attn_mma5<<<dim3(S_ / QT, B_ * HQ_), 256, ATT_SMEM>>>(qh, kh, vth, ah);

    // output projection -> d_out (fp32)
    gemm_fp16<<<dim3(D_ / 128, M / 128), 256, GSMEM>>>(
        ah, woh, out, nullptr, nullptr, nullptr, M, D_, D_, 0, fc, fs);
}